// round 1
// baseline (speedup 1.0000x reference)
#include <cuda_runtime.h>
#include <stdint.h>

// Problem constants (fixed instance: n=5003, K=3, k=1, num_sample=100)
#define NN      5003
#define NSAMPLE 100
#define KSEL    1
#define TPB     512
#define NWARP   (TPB / 32)

// JAX threefry mode:
//  1 = partitionable (default since jax 0.4.30): bits[i] = o0 ^ o1 of
//      threefry2x32(key, (hi32(i)=0, lo32(i)=i))
//  0 = legacy split-iota scheme (pre-0.4.30)
#define GUMBEL_MODE_PARTITIONABLE 1

__device__ double g_sumExp[NN];
__device__ float  g_logZ[NN];
__device__ double g_logp;

// ---------------------------------------------------------------------------
// threefry2x32 with key = (0, 42)  (jax.random.key(42) -> data [0, 42])
// ---------------------------------------------------------------------------
__device__ __forceinline__ void threefry2x32(uint32_t x0, uint32_t x1,
                                             uint32_t &o0, uint32_t &o1) {
  const uint32_t ks0 = 0u;
  const uint32_t ks1 = 42u;
  const uint32_t ks2 = 0x1BD11BDAu ^ ks0 ^ ks1;
#define TF_R(r) { x0 += x1; x1 = __funnelshift_l(x1, x1, (r)); x1 ^= x0; }
  x0 += ks0; x1 += ks1;
  TF_R(13) TF_R(15) TF_R(26) TF_R(6)
  x0 += ks1; x1 += ks2 + 1u;
  TF_R(17) TF_R(29) TF_R(16) TF_R(24)
  x0 += ks2; x1 += ks0 + 2u;
  TF_R(13) TF_R(15) TF_R(26) TF_R(6)
  x0 += ks0; x1 += ks1 + 3u;
  TF_R(17) TF_R(29) TF_R(16) TF_R(24)
  x0 += ks1; x1 += ks2 + 4u;
  TF_R(13) TF_R(15) TF_R(26) TF_R(6)
  x0 += ks2; x1 += ks0 + 5u;
#undef TF_R
  o0 = x0; o1 = x1;
}

__device__ __forceinline__ uint32_t random_bits_at(uint32_t idx) {
#if GUMBEL_MODE_PARTITIONABLE
  uint32_t o0, o1;
  threefry2x32(0u, idx, o0, o1);
  return o0 ^ o1;
#else
  // legacy: counts = iota(size), odd size padded with one 0, split in halves
  const uint32_t SZ = (uint32_t)NN * (uint32_t)NN;   // 25030009 (odd)
  const uint32_t H  = (SZ + 1u) / 2u;                // 12515005
  uint32_t p  = (idx < H) ? idx : (idx - H);
  uint32_t x1 = H + p;
  if (x1 > SZ - 1u) x1 = 0u;                         // the zero pad element
  uint32_t o0, o1;
  threefry2x32(p, x1, o0, o1);
  return (idx < H) ? o0 : o1;
#endif
}

// jax.random.gumbel elementwise: u = max(tiny, f32_in_[0,1) + tiny); -log(-log(u))
__device__ __forceinline__ float gumbel_at(uint32_t idx) {
  uint32_t bits = random_bits_at(idx);
  uint32_t fb = (bits >> 9) | 0x3F800000u;
  float f = __uint_as_float(fb) - 1.0f;              // exact
  const float tiny = 1.17549435e-38f;
  float u = fmaxf(tiny, __fadd_rn(f, tiny));         // (maxval-minval)==1.0f exactly
  return -logf(-logf(u));
}

// ---------------------------------------------------------------------------
// Kernels
// ---------------------------------------------------------------------------
__global__ void k_zero(float *__restrict__ out, size_t total) {
  size_t i = (size_t)blockIdx.x * blockDim.x + threadIdx.x;
  size_t stride = (size_t)gridDim.x * blockDim.x;
  for (size_t j = i; j < total; j += stride) out[j] = 0.0f;
  for (size_t j = i; j < (size_t)NN; j += stride) g_sumExp[j] = 0.0;
  if (i == 0) g_logp = 0.0;
}

__global__ void k_edges(const int *__restrict__ ei, int ne, float *__restrict__ C) {
  int e = blockIdx.x * blockDim.x + threadIdx.x;
  if (e < ne) {
    int s = ei[e];
    int d = ei[ne + e];
    C[(size_t)s * NN + d] = 1.0f;
  }
}

__global__ void k_colsum(const float *__restrict__ Bk, int rows_per) {
  int c = blockIdx.x * blockDim.x + threadIdx.x;
  if (c >= NN) return;
  int r0 = blockIdx.y * rows_per;
  int r1 = min(r0 + rows_per, NN);
  double acc = 0.0;
  for (int r = r0; r < r1; r++)
    acc += (double)expf(Bk[(size_t)r * NN + c]);
  atomicAdd(&g_sumExp[c], acc);
}

__global__ void k_logz() {
  int c = blockIdx.x * blockDim.x + threadIdx.x;
  if (c < NN) g_logZ[c] = logf((float)g_sumExp[c]);
}

// One block per row r: build keys, exact 48-bit radix select of top-NSAMPLE,
// flip C[s*NN + r], and accumulate sum(Bk[s, r]) - logZ[r] into g_logp.
__global__ __launch_bounds__(TPB) void k_topk(const float *__restrict__ Bk,
                                              float *__restrict__ C) {
  __shared__ unsigned long long keys[NN];
  __shared__ unsigned int hist[256];
  __shared__ double warpsum[NWARP];
  __shared__ unsigned long long sh_prefix;
  __shared__ int sh_kk;

  const int r = blockIdx.x;
  const int tid = threadIdx.x;
  const uint32_t base = (uint32_t)r * (uint32_t)NN;

  // Build composite keys: hi 32 = order-preserving float bits of
  // v = (Bk[r,c] - logZ[c]) + gumbel[r,c]; lo 16 = 0xFFFF - c (ties -> low c wins)
  for (int c = tid; c < NN; c += TPB) {
    float b = Bk[base + c];
    float g = gumbel_at(base + (uint32_t)c);
    float v = __fadd_rn(__fsub_rn(b, g_logZ[c]), g);
    uint32_t fb = __float_as_uint(v);
    fb = (fb & 0x80000000u) ? ~fb : (fb | 0x80000000u);
    keys[c] = ((unsigned long long)fb << 16) |
              (unsigned long long)(0xFFFFu - (uint32_t)c);
  }
  if (tid == 0) { sh_prefix = 0ull; sh_kk = NSAMPLE; }
  __syncthreads();

  // 6 x 8-bit MSB-first radix refinement over the 48-bit keys
  for (int shift = 40; shift >= 0; shift -= 8) {
    if (tid < 256) hist[tid] = 0u;
    __syncthreads();
    unsigned long long pref = sh_prefix;
    int hs = shift + 8;
    for (int c = tid; c < NN; c += TPB) {
      unsigned long long kk = keys[c];
      if ((kk >> hs) == (pref >> hs))
        atomicAdd(&hist[(unsigned)((kk >> shift) & 0xFFull)], 1u);
    }
    __syncthreads();
    if (tid == 0) {
      int need = sh_kk;
      unsigned cum = 0;
      for (int d = 255; d >= 0; d--) {
        unsigned greater = cum;
        cum += hist[d];
        if ((int)cum >= need) {
          sh_prefix = pref | ((unsigned long long)d << shift);
          sh_kk = need - (int)greater;
          break;
        }
      }
    }
    __syncthreads();
  }

  // Keys are unique (index embedded) -> exactly NSAMPLE keys >= threshold.
  const unsigned long long T = sh_prefix;
  double local = 0.0;
  for (int c = tid; c < NN; c += TPB) {
    if (keys[c] >= T) {
      size_t idx = (size_t)c * NN + r;   // M[s=c, i=r] -> flip C[c, r]
      local += (double)Bk[idx];          // vals[i,j] = Bk[S[i,j], i]
      C[idx] = 1.0f - C[idx];            // C = A + M*(1-2A)
    }
  }
  // block reduce (double) and accumulate log_p contribution
  #pragma unroll
  for (int off = 16; off; off >>= 1)
    local += __shfl_down_sync(0xFFFFFFFFu, local, off);
  if ((tid & 31) == 0) warpsum[tid >> 5] = local;
  __syncthreads();
  if (tid == 0) {
    double t = 0.0;
    #pragma unroll
    for (int w = 0; w < NWARP; w++) t += warpsum[w];
    atomicAdd(&g_logp, t - (double)g_logZ[r]);
  }
}

__global__ void k_final(float *__restrict__ out, size_t pos) {
  if (threadIdx.x == 0) out[pos] = (float)g_logp;
}

// ---------------------------------------------------------------------------
// Launch
// ---------------------------------------------------------------------------
extern "C" void kernel_launch(void *const *d_in, const int *in_sizes, int n_in,
                              void *d_out, int out_size) {
  const int   *ei = (const int *)d_in[0];               // edge_index [2, n_edges] int32
  const float *B  = (const float *)d_in[1];             // B [K, n, n] float32
  const int ne = in_sizes[0] / 2;
  const float *Bk = B + (size_t)KSEL * NN * NN;
  float *out = (float *)d_out;
  const size_t total = (size_t)out_size;

  k_zero<<<512, 256>>>(out, total);
  k_edges<<<(ne + 255) / 256, 256>>>(ei, ne, out);

  const int row_chunks = 16;
  const int rows_per = (NN + row_chunks - 1) / row_chunks;
  dim3 gcs((NN + 255) / 256, row_chunks);
  k_colsum<<<gcs, 256>>>(Bk, rows_per);
  k_logz<<<(NN + 255) / 256, 256>>>();

  k_topk<<<NN, TPB>>>(Bk, out);

  const size_t pos = (size_t)NN * NN;
  if (pos < total) k_final<<<1, 32>>>(out, pos);
}

// round 2
// speedup vs baseline: 1.8134x; 1.8134x over previous
#include <cuda_runtime.h>
#include <stdint.h>

// Problem constants (fixed instance: n=5003, K=3, k=1, num_sample=100)
#define NN      5003
#define NSAMPLE 100
#define KSEL    1
#define TPB     512
#define NWARP   (TPB / 32)
#define NITER   ((NN + TPB - 1) / TPB)   // 10

__device__ double g_sumExp[NN];
__device__ float  g_logZ[NN];
__device__ double g_logp;

// ---------------------------------------------------------------------------
// threefry2x32, key = (0, 42); partitionable mode: bits = o0 ^ o1 @ ctr (0, i)
// ---------------------------------------------------------------------------
__device__ __forceinline__ void threefry2x32(uint32_t x0, uint32_t x1,
                                             uint32_t &o0, uint32_t &o1) {
  const uint32_t ks0 = 0u;
  const uint32_t ks1 = 42u;
  const uint32_t ks2 = 0x1BD11BDAu ^ ks0 ^ ks1;
#define TF_R(r) { x0 += x1; x1 = __funnelshift_l(x1, x1, (r)); x1 ^= x0; }
  x0 += ks0; x1 += ks1;
  TF_R(13) TF_R(15) TF_R(26) TF_R(6)
  x0 += ks1; x1 += ks2 + 1u;
  TF_R(17) TF_R(29) TF_R(16) TF_R(24)
  x0 += ks2; x1 += ks0 + 2u;
  TF_R(13) TF_R(15) TF_R(26) TF_R(6)
  x0 += ks0; x1 += ks1 + 3u;
  TF_R(17) TF_R(29) TF_R(16) TF_R(24)
  x0 += ks1; x1 += ks2 + 4u;
  TF_R(13) TF_R(15) TF_R(26) TF_R(6)
  x0 += ks2; x1 += ks0 + 5u;
#undef TF_R
  o0 = x0; o1 = x1;
}

__device__ __forceinline__ float gumbel_at(uint32_t idx) {
  uint32_t o0, o1;
  threefry2x32(0u, idx, o0, o1);
  uint32_t bits = o0 ^ o1;
  uint32_t fb = (bits >> 9) | 0x3F800000u;
  float f = __uint_as_float(fb) - 1.0f;             // exact
  const float tiny = 1.17549435e-38f;
  float u = fmaxf(tiny, __fadd_rn(f, tiny));
  // selection-only accuracy: fast log path (see round analysis)
  return -__logf(-__logf(u));
}

// ---------------------------------------------------------------------------
// Kernels
// ---------------------------------------------------------------------------
__global__ void k_zero(float *__restrict__ out, size_t total) {
  size_t i = (size_t)blockIdx.x * blockDim.x + threadIdx.x;
  size_t stride = (size_t)gridDim.x * blockDim.x;
  size_t nv4 = total >> 2;
  float4 *o4 = (float4 *)out;
  float4 z4 = make_float4(0.f, 0.f, 0.f, 0.f);
  for (size_t j = i; j < nv4; j += stride) o4[j] = z4;
  for (size_t j = (nv4 << 2) + i; j < total; j += stride) out[j] = 0.0f;
  for (size_t j = i; j < (size_t)NN; j += stride) g_sumExp[j] = 0.0;
  if (i == 0) g_logp = 0.0;
}

__global__ void k_edges(const int *__restrict__ ei, int ne, float *__restrict__ C) {
  int e = blockIdx.x * blockDim.x + threadIdx.x;
  if (e < ne) {
    int s = ei[e];
    int d = ei[ne + e];
    C[(size_t)s * NN + d] = 1.0f;
  }
}

__global__ void k_colsum(const float *__restrict__ Bk, int rows_per) {
  int c = blockIdx.x * blockDim.x + threadIdx.x;
  if (c >= NN) return;
  int r0 = blockIdx.y * rows_per;
  int r1 = min(r0 + rows_per, NN);
  float a0 = 0.f, a1 = 0.f, a2 = 0.f, a3 = 0.f;
  int r = r0;
  for (; r + 3 < r1; r += 4) {
    a0 += __expf(Bk[(size_t)(r + 0) * NN + c]);
    a1 += __expf(Bk[(size_t)(r + 1) * NN + c]);
    a2 += __expf(Bk[(size_t)(r + 2) * NN + c]);
    a3 += __expf(Bk[(size_t)(r + 3) * NN + c]);
  }
  for (; r < r1; r++) a0 += __expf(Bk[(size_t)r * NN + c]);
  atomicAdd(&g_sumExp[c], (double)((a0 + a1) + (a2 + a3)));
}

__global__ void k_logz() {
  int c = blockIdx.x * blockDim.x + threadIdx.x;
  if (c < NN) g_logZ[c] = logf((float)g_sumExp[c]);
}

// ---------------------------------------------------------------------------
// Per-row exact top-NSAMPLE radix select (32-bit float-ordered keys,
// lowest-index tie break), flip C, accumulate log_p.
// ---------------------------------------------------------------------------
__global__ __launch_bounds__(TPB) void k_topk(const float *__restrict__ Bk,
                                              float *__restrict__ C) {
  __shared__ uint32_t keys[NN];
  __shared__ unsigned short cand[NN];
  __shared__ unsigned int hist[256];
  __shared__ double warpsum[NWARP];
  __shared__ int sh_need, sh_d, sh_m, sh_eqn;

  const int r = blockIdx.x;
  const int tid = threadIdx.x;
  const int lane = tid & 31;
  const uint32_t base = (uint32_t)r * (uint32_t)NN;

  if (tid < 256) hist[tid] = 0u;
  if (tid == 0) { sh_need = NSAMPLE; sh_m = 0; sh_eqn = 0; }
  __syncthreads();

  // ---- build keys + pass 1 histogram (byte 3), match-aggregated atomics ----
  #pragma unroll 2
  for (int j = 0; j < NITER; j++) {
    int c = tid + j * TPB;
    unsigned int bin = 0xFFFFu;
    if (c < NN) {
      float b = Bk[base + (uint32_t)c];
      float g = gumbel_at(base + (uint32_t)c);
      float v = __fadd_rn(__fsub_rn(b, g_logZ[c]), g);
      uint32_t fb = __float_as_uint(v);
      fb = (fb & 0x80000000u) ? ~fb : (fb | 0x80000000u);
      keys[c] = fb;
      bin = fb >> 24;
    }
    unsigned int mm = __match_any_sync(0xFFFFFFFFu, bin);
    if ((int)(__ffs(mm) - 1) == lane && bin < 256u)
      atomicAdd(&hist[bin], __popc(mm));
  }
  __syncthreads();

  // warp-parallel descending bin select: sets sh_d, updates sh_need
#define BIN_SELECT()                                                         \
  if (tid < 32) {                                                            \
    int b0 = 255 - 8 * tid;                                                  \
    unsigned int psum = 0;                                                   \
    _Pragma("unroll")                                                        \
    for (int i = 0; i < 8; i++) psum += hist[b0 - i];                        \
    unsigned int pre = psum;                                                 \
    _Pragma("unroll")                                                        \
    for (int off = 1; off < 32; off <<= 1) {                                 \
      unsigned int v = __shfl_up_sync(0xFFFFFFFFu, pre, off);                \
      if (tid >= off) pre += v;                                              \
    }                                                                        \
    unsigned int excl = pre - psum;                                          \
    int need = sh_need;                                                      \
    __syncwarp();                                                            \
    if ((int)excl < need && (int)(excl + psum) >= need) {                    \
      unsigned int cum = excl;                                               \
      _Pragma("unroll")                                                      \
      for (int i = 0; i < 8; i++) {                                          \
        unsigned int h = hist[b0 - i];                                       \
        if ((int)(cum + h) >= need) {                                        \
          sh_d = b0 - i; sh_need = need - (int)cum; break;                   \
        }                                                                    \
        cum += h;                                                            \
      }                                                                      \
    }                                                                        \
  }                                                                          \
  __syncthreads();

  BIN_SELECT();
  const int d3 = sh_d;
  if (tid < 256) hist[tid] = 0u;
  __syncthreads();

  // ---- compact byte3==d3 into cand[] + pass 2 histogram (byte 2) ----
  #pragma unroll 2
  for (int j = 0; j < NITER; j++) {
    int c = tid + j * TPB;
    bool p = (c < NN) && ((keys[c] >> 24) == (unsigned)d3);
    unsigned int mask = __ballot_sync(0xFFFFFFFFu, p);
    if (mask) {
      int leader = __ffs(mask) - 1;
      int basep = 0;
      if (lane == leader) basep = atomicAdd(&sh_m, __popc(mask));
      basep = __shfl_sync(0xFFFFFFFFu, basep, leader);
      if (p) cand[basep + __popc(mask & ((1u << lane) - 1u))] = (unsigned short)c;
    }
    unsigned int bin = p ? ((keys[c] >> 16) & 255u) : 0xFFFFu;
    unsigned int mm = __match_any_sync(0xFFFFFFFFu, bin);
    if ((int)(__ffs(mm) - 1) == lane && bin < 256u)
      atomicAdd(&hist[bin], __popc(mm));
  }
  __syncthreads();

  BIN_SELECT();
  const int d2 = sh_d;
  const int m = sh_m;
  if (tid < 256) hist[tid] = 0u;
  __syncthreads();

  // ---- pass 3 (byte 1) over candidates ----
  const int miters = (m + TPB - 1) / TPB;
  for (int j = 0; j < miters; j++) {
    int i = tid + j * TPB;
    unsigned int bin = 0xFFFFu;
    if (i < m) {
      uint32_t kk = keys[cand[i]];
      if (((kk >> 16) & 255u) == (unsigned)d2) bin = (kk >> 8) & 255u;
    }
    unsigned int mm = __match_any_sync(0xFFFFFFFFu, bin);
    if ((int)(__ffs(mm) - 1) == lane && bin < 256u)
      atomicAdd(&hist[bin], __popc(mm));
  }
  __syncthreads();

  BIN_SELECT();
  const int d1 = sh_d;
  if (tid < 256) hist[tid] = 0u;
  __syncthreads();

  // ---- pass 4 (byte 0) over candidates ----
  const unsigned int mid = ((unsigned)d2 << 8) | (unsigned)d1;
  for (int j = 0; j < miters; j++) {
    int i = tid + j * TPB;
    unsigned int bin = 0xFFFFu;
    if (i < m) {
      uint32_t kk = keys[cand[i]];
      if (((kk >> 8) & 0xFFFFu) == mid) bin = kk & 255u;
    }
    unsigned int mm = __match_any_sync(0xFFFFFFFFu, bin);
    if ((int)(__ffs(mm) - 1) == lane && bin < 256u)
      atomicAdd(&hist[bin], __popc(mm));
  }
  __syncthreads();

  BIN_SELECT();
  const int d0 = sh_d;
  const int need_eq = sh_need;   // number of key==T elements to take
  const uint32_t T = ((uint32_t)d3 << 24) | ((uint32_t)d2 << 16) |
                     ((uint32_t)d1 << 8) | (uint32_t)d0;

  // ---- epilogue: select, flip C, accumulate log_p ----
  double local = 0.0;
  for (int c = tid; c < NN; c += TPB) {
    uint32_t kk = keys[c];
    if (kk > T) {
      size_t idx = (size_t)c * NN + r;     // M[s=c, i=r] -> flip C[c, r]
      local += (double)Bk[idx];
      C[idx] = 1.0f - C[idx];
    } else if (kk == T) {
      int p = atomicAdd(&sh_eqn, 1);
      cand[p] = (unsigned short)c;         // cand[] is free now
    }
  }
  __syncthreads();
  const int ne = sh_eqn;                   // >= need_eq >= 1
  for (int i = tid; i < ne; i += TPB) {
    int ci = cand[i];
    int rank = 0;
    for (int jj = 0; jj < ne; jj++) rank += (cand[jj] < ci);
    if (rank < need_eq) {                  // lowest-index-first tie break
      size_t idx = (size_t)ci * NN + r;
      local += (double)Bk[idx];
      C[idx] = 1.0f - C[idx];
    }
  }

  // block reduce (double) then one global atomic
  #pragma unroll
  for (int off = 16; off; off >>= 1)
    local += __shfl_down_sync(0xFFFFFFFFu, local, off);
  if (lane == 0) warpsum[tid >> 5] = local;
  __syncthreads();
  if (tid == 0) {
    double t = 0.0;
    #pragma unroll
    for (int w = 0; w < NWARP; w++) t += warpsum[w];
    atomicAdd(&g_logp, t - (double)g_logZ[r]);
  }
}

__global__ void k_final(float *__restrict__ out, size_t pos) {
  if (threadIdx.x == 0) out[pos] = (float)g_logp;
}

// ---------------------------------------------------------------------------
// Launch
// ---------------------------------------------------------------------------
extern "C" void kernel_launch(void *const *d_in, const int *in_sizes, int n_in,
                              void *d_out, int out_size) {
  const int   *ei = (const int *)d_in[0];     // edge_index [2, n_edges] int32
  const float *B  = (const float *)d_in[1];   // B [K, n, n] float32
  const int ne = in_sizes[0] / 2;
  const float *Bk = B + (size_t)KSEL * NN * NN;
  float *out = (float *)d_out;
  const size_t total = (size_t)out_size;

  k_zero<<<2048, 256>>>(out, total);
  k_edges<<<(ne + 255) / 256, 256>>>(ei, ne, out);

  const int row_chunks = 16;
  const int rows_per = (NN + row_chunks - 1) / row_chunks;
  dim3 gcs((NN + 255) / 256, row_chunks);
  k_colsum<<<gcs, 256>>>(Bk, rows_per);
  k_logz<<<(NN + 255) / 256, 256>>>();

  k_topk<<<NN, TPB>>>(Bk, out);

  const size_t pos = (size_t)NN * NN;
  if (pos < total) k_final<<<1, 32>>>(out, pos);
}